// round 1
// baseline (speedup 1.0000x reference)
#include <cuda_runtime.h>

// ---------------- problem constants ----------------
#define N_SRC 100000
#define ND0 50000
#define ND1 25000
#define ND2 12500
#define E0  500000
#define E1  250000
#define E2  125000
#define DIM 256   // hidden/input feature dim (K per matrix)

// ---------------- device scratch (static, no allocs) ----------------
__device__ float g_mean[(size_t)ND0 * DIM];   // mean-aggregated features (reused per layer)
__device__ float g_h0[(size_t)ND0 * DIM];     // layer-0 output
__device__ float g_h1[(size_t)ND1 * DIM];     // layer-1 output
__device__ int   g_deg[ND0];
__device__ int   g_rowptr[ND0 + 1];
__device__ int   g_cursor[ND0];
__device__ int   g_srcidx[E0];                // CSR payload: source node per slot

// ---------------- CSR build ----------------
__global__ void k_zero_deg(int n) {
    int i = blockIdx.x * blockDim.x + threadIdx.x;
    if (i < n) g_deg[i] = 0;
}

__global__ void k_hist(const int* __restrict__ dst, int E) {
    int i = blockIdx.x * blockDim.x + threadIdx.x;
    if (i < E) atomicAdd(&g_deg[dst[i]], 1);
}

// single-block exclusive scan over g_deg -> g_rowptr / g_cursor
__global__ void k_scan(int n) {
    __shared__ int sdata[1024];
    __shared__ int carry;
    if (threadIdx.x == 0) carry = 0;
    __syncthreads();
    for (int base = 0; base < n; base += 1024) {
        int i = base + threadIdx.x;
        int v = (i < n) ? g_deg[i] : 0;
        sdata[threadIdx.x] = v;
        __syncthreads();
        #pragma unroll
        for (int off = 1; off < 1024; off <<= 1) {
            int t = (threadIdx.x >= off) ? sdata[threadIdx.x - off] : 0;
            __syncthreads();
            sdata[threadIdx.x] += t;
            __syncthreads();
        }
        int excl = sdata[threadIdx.x] - v;
        int c = carry;
        if (i < n) {
            g_rowptr[i] = c + excl;
            g_cursor[i] = c + excl;
        }
        __syncthreads();
        if (threadIdx.x == 0) carry = c + sdata[1023];
        __syncthreads();
    }
    if (threadIdx.x == 0) g_rowptr[n] = carry;
}

__global__ void k_fill(const int* __restrict__ src, const int* __restrict__ dst, int E) {
    int i = blockIdx.x * blockDim.x + threadIdx.x;
    if (i < E) {
        int pos = atomicAdd(&g_cursor[dst[i]], 1);
        g_srcidx[pos] = src[i];
    }
}

// ---------------- aggregation: one warp per dst row, pull-style ----------------
__global__ void k_aggregate(const float* __restrict__ h, int n_dst) {
    int gw   = (blockIdx.x * blockDim.x + threadIdx.x) >> 5;
    int lane = threadIdx.x & 31;
    if (gw >= n_dst) return;
    int s = g_rowptr[gw], e = g_rowptr[gw + 1];
    float4 a0 = make_float4(0.f, 0.f, 0.f, 0.f);
    float4 a1 = make_float4(0.f, 0.f, 0.f, 0.f);
    for (int i = s; i < e; i++) {
        const float4* row = (const float4*)(h + (size_t)g_srcidx[i] * DIM);
        float4 x0 = __ldg(&row[lane]);
        float4 x1 = __ldg(&row[lane + 32]);
        a0.x += x0.x; a0.y += x0.y; a0.z += x0.z; a0.w += x0.w;
        a1.x += x1.x; a1.y += x1.y; a1.z += x1.z; a1.w += x1.w;
    }
    float inv = 1.0f / (float)max(e - s, 1);
    a0.x *= inv; a0.y *= inv; a0.z *= inv; a0.w *= inv;
    a1.x *= inv; a1.y *= inv; a1.z *= inv; a1.w *= inv;
    float4* o = (float4*)(g_mean + (size_t)gw * DIM);
    o[lane]      = a0;
    o[lane + 32] = a1;
}

// ---------------- fused GEMM: out = A0@W0 + A1@W1 + bias (optional relu) ----------------
// A0, A1: [M, 256] row-major. W0, W1: [256, N] row-major. out: [M, N].
__global__ __launch_bounds__(256) void k_gemm(
    const float* __restrict__ A0, const float* __restrict__ A1,
    const float* __restrict__ W0, const float* __restrict__ W1,
    const float* __restrict__ bias, float* __restrict__ out,
    int M, int N, int relu)
{
    const int BM = 128, BN = 128, BK = 8;
    __shared__ float As[BK][BM];
    __shared__ float Bs[BK][BN];
    int tid  = threadIdx.x;
    int brow = blockIdx.y * BM;
    int bcol = blockIdx.x * BN;
    int a_r = tid >> 1, a_c = (tid & 1) * 4;
    int b_r = tid >> 5, b_c = (tid & 31) * 4;
    int ty = (tid >> 4) * 8, tx = (tid & 15) * 8;

    float acc[8][8];
    #pragma unroll
    for (int i = 0; i < 8; i++)
        #pragma unroll
        for (int j = 0; j < 8; j++) acc[i][j] = 0.f;

    #pragma unroll
    for (int phase = 0; phase < 2; phase++) {
        const float* A = phase ? A1 : A0;
        const float* W = phase ? W1 : W0;
        for (int k0 = 0; k0 < DIM; k0 += BK) {
            int gr = brow + a_r;
            float4 av = (gr < M) ? *(const float4*)(A + (size_t)gr * DIM + k0 + a_c)
                                 : make_float4(0.f, 0.f, 0.f, 0.f);
            As[a_c + 0][a_r] = av.x;
            As[a_c + 1][a_r] = av.y;
            As[a_c + 2][a_r] = av.z;
            As[a_c + 3][a_r] = av.w;
            *(float4*)&Bs[b_r][b_c] =
                *(const float4*)(W + (size_t)(k0 + b_r) * N + bcol + b_c);
            __syncthreads();
            #pragma unroll
            for (int k = 0; k < BK; k++) {
                float ra[8], rb[8];
                #pragma unroll
                for (int i = 0; i < 8; i++) ra[i] = As[k][ty + i];
                #pragma unroll
                for (int j = 0; j < 8; j++) rb[j] = Bs[k][tx + j];
                #pragma unroll
                for (int i = 0; i < 8; i++)
                    #pragma unroll
                    for (int j = 0; j < 8; j++)
                        acc[i][j] += ra[i] * rb[j];
            }
            __syncthreads();
        }
    }

    #pragma unroll
    for (int i = 0; i < 8; i++) {
        int gr = brow + ty + i;
        if (gr < M) {
            #pragma unroll
            for (int j = 0; j < 8; j += 4) {
                float4 v;
                v.x = acc[i][j + 0] + bias[bcol + tx + j + 0];
                v.y = acc[i][j + 1] + bias[bcol + tx + j + 1];
                v.z = acc[i][j + 2] + bias[bcol + tx + j + 2];
                v.w = acc[i][j + 3] + bias[bcol + tx + j + 3];
                if (relu) {
                    v.x = fmaxf(v.x, 0.f); v.y = fmaxf(v.y, 0.f);
                    v.z = fmaxf(v.z, 0.f); v.w = fmaxf(v.w, 0.f);
                }
                *(float4*)(out + (size_t)gr * N + bcol + tx + j) = v;
            }
        }
    }
}

// ---------------- host orchestration ----------------
static void run_layer(const float* h_in, int n_dst, int E,
                      const int* src, const int* dst,
                      const float* Wn, const float* Ws, const float* b,
                      float* h_out, int N_out, int relu,
                      float* mean_ptr)
{
    k_zero_deg<<<(n_dst + 255) / 256, 256>>>(n_dst);
    k_hist<<<(E + 255) / 256, 256>>>(dst, E);
    k_scan<<<1, 1024>>>(n_dst);
    k_fill<<<(E + 255) / 256, 256>>>(src, dst, E);
    k_aggregate<<<(n_dst + 7) / 8, 256>>>(h_in, n_dst);
    dim3 grid(N_out / 128, (n_dst + 127) / 128);
    k_gemm<<<grid, 256>>>(mean_ptr, h_in, Wn, Ws, b, h_out, n_dst, N_out, relu);
}

extern "C" void kernel_launch(void* const* d_in, const int* in_sizes, int n_in,
                              void* d_out, int out_size)
{
    const float* x   = (const float*)d_in[0];
    const float* Wn0 = (const float*)d_in[1];
    const float* Ws0 = (const float*)d_in[2];
    const float* b0  = (const float*)d_in[3];
    const float* Wn1 = (const float*)d_in[4];
    const float* Ws1 = (const float*)d_in[5];
    const float* b1  = (const float*)d_in[6];
    const float* Wn2 = (const float*)d_in[7];
    const float* Ws2 = (const float*)d_in[8];
    const float* b2  = (const float*)d_in[9];
    const int* src0 = (const int*)d_in[10];
    const int* dst0 = (const int*)d_in[11];
    const int* src1 = (const int*)d_in[12];
    const int* dst1 = (const int*)d_in[13];
    const int* src2 = (const int*)d_in[14];
    const int* dst2 = (const int*)d_in[15];

    float *p_mean, *p_h0, *p_h1;
    cudaGetSymbolAddress((void**)&p_mean, g_mean);
    cudaGetSymbolAddress((void**)&p_h0, g_h0);
    cudaGetSymbolAddress((void**)&p_h1, g_h1);

    // Layer 0: x[100000,256] -> h0[50000,256], relu
    run_layer(x,    ND0, E0, src0, dst0, Wn0, Ws0, b0, p_h0, 256, 1, p_mean);
    // Layer 1: h0 -> h1[25000,256], relu
    run_layer(p_h0, ND1, E1, src1, dst1, Wn1, Ws1, b1, p_h1, 256, 1, p_mean);
    // Layer 2: h1 -> out[12500,128], no relu
    run_layer(p_h1, ND2, E2, src2, dst2, Wn2, Ws2, b2, (float*)d_out, 128, 0, p_mean);
}

// round 6
// speedup vs baseline: 1.6279x; 1.6279x over previous
#include <cuda_runtime.h>
#include <cuda_bf16.h>
#include <cstdint>

// ---------------- problem constants ----------------
#define ND0 50000
#define ND1 25000
#define ND2 12500
#define E0  500000
#define DIM 256
#define NB0 391                 // ceil(ND0/128)
#define MAXROWS (NB0 * 128)     // 50048 padded rows for A images

// ---------------- device scratch (static, no allocs) ----------------
__device__ float g_mean[(size_t)ND0 * DIM];
__device__ float g_h0[(size_t)ND0 * DIM];
__device__ float g_h1[(size_t)ND1 * DIM];
__device__ int g_deg[ND0];
__device__ int g_rowptr[ND0 + 1];
__device__ int g_cursor[ND0];
__device__ int g_srcidx[E0];
// A operand images, row-major [MAXROWS, 256] bf16 (hi / lo, mean / self)
__device__ __align__(16) __nv_bfloat16 g_Amh[(size_t)MAXROWS * DIM];
__device__ __align__(16) __nv_bfloat16 g_Aml[(size_t)MAXROWS * DIM];
__device__ __align__(16) __nv_bfloat16 g_Ash[(size_t)MAXROWS * DIM];
__device__ __align__(16) __nv_bfloat16 g_Asl[(size_t)MAXROWS * DIM];
// weight images: 6 matrices, each hi[256*N] then lo[256*N] bf16 (N<=256)
__device__ __align__(16) __nv_bfloat16 g_W[6][2 * 256 * 256];

// ---------------- helpers ----------------
__device__ __forceinline__ uint32_t smem_u32(const void* p) {
    uint32_t a;
    asm("{ .reg .u64 t; cvta.to.shared.u64 t, %1; cvt.u32.u64 %0, t; }" : "=r"(a) : "l"(p));
    return a;
}
__device__ __forceinline__ void cp16(uint32_t dst, const void* src) {
    asm volatile("cp.async.cg.shared.global [%0], [%1], 16;" :: "r"(dst), "l"(src) : "memory");
}
__device__ __forceinline__ void ldmatrix_x4(uint32_t* r, uint32_t addr) {
    asm volatile("ldmatrix.sync.aligned.m8n8.x4.shared.b16 {%0,%1,%2,%3}, [%4];"
                 : "=r"(r[0]), "=r"(r[1]), "=r"(r[2]), "=r"(r[3]) : "r"(addr));
}
__device__ __forceinline__ void ldmatrix_x4_t(uint32_t* r, uint32_t addr) {
    asm volatile("ldmatrix.sync.aligned.m8n8.x4.trans.shared.b16 {%0,%1,%2,%3}, [%4];"
                 : "=r"(r[0]), "=r"(r[1]), "=r"(r[2]), "=r"(r[3]) : "r"(addr));
}
__device__ __forceinline__ void mma_bf16(float* c, const uint32_t* a, uint32_t b0, uint32_t b1) {
    asm volatile(
        "mma.sync.aligned.m16n8k16.row.col.f32.bf16.bf16.f32 "
        "{%0,%1,%2,%3}, {%4,%5,%6,%7}, {%8,%9}, {%0,%1,%2,%3};"
        : "+f"(c[0]), "+f"(c[1]), "+f"(c[2]), "+f"(c[3])
        : "r"(a[0]), "r"(a[1]), "r"(a[2]), "r"(a[3]), "r"(b0), "r"(b1));
}

// ---------------- CSR build ----------------
__global__ void k_zero_deg(int n) {
    int i = blockIdx.x * blockDim.x + threadIdx.x;
    if (i < n) g_deg[i] = 0;
}
__global__ void k_hist(const int* __restrict__ dst, int E) {
    int i = blockIdx.x * blockDim.x + threadIdx.x;
    if (i < E) atomicAdd(&g_deg[dst[i]], 1);
}
__global__ void k_scan(int n) {
    __shared__ int sdata[1024];
    __shared__ int carry;
    if (threadIdx.x == 0) carry = 0;
    __syncthreads();
    for (int base = 0; base < n; base += 1024) {
        int i = base + threadIdx.x;
        int v = (i < n) ? g_deg[i] : 0;
        sdata[threadIdx.x] = v;
        __syncthreads();
        #pragma unroll
        for (int off = 1; off < 1024; off <<= 1) {
            int t = (threadIdx.x >= off) ? sdata[threadIdx.x - off] : 0;
            __syncthreads();
            sdata[threadIdx.x] += t;
            __syncthreads();
        }
        int excl = sdata[threadIdx.x] - v;
        int c = carry;
        if (i < n) { g_rowptr[i] = c + excl; g_cursor[i] = c + excl; }
        __syncthreads();
        if (threadIdx.x == 0) carry = c + sdata[1023];
        __syncthreads();
    }
    if (threadIdx.x == 0) g_rowptr[n] = carry;
}
__global__ void k_fill(const int* __restrict__ src, const int* __restrict__ dst, int E) {
    int i = blockIdx.x * blockDim.x + threadIdx.x;
    if (i < E) {
        int pos = atomicAdd(&g_cursor[dst[i]], 1);
        g_srcidx[pos] = src[i];
    }
}

// ---------------- aggregation: one warp per dst row ----------------
__global__ void k_aggregate(const float* __restrict__ h, int n_dst) {
    int gw = (blockIdx.x * blockDim.x + threadIdx.x) >> 5;
    int lane = threadIdx.x & 31;
    if (gw >= n_dst) return;
    int s = g_rowptr[gw], e = g_rowptr[gw + 1];
    float4 a0 = make_float4(0.f, 0.f, 0.f, 0.f);
    float4 a1 = make_float4(0.f, 0.f, 0.f, 0.f);
    for (int i = s; i < e; i++) {
        const float4* row = (const float4*)(h + (size_t)g_srcidx[i] * DIM);
        float4 x0 = __ldg(&row[lane]);
        float4 x1 = __ldg(&row[lane + 32]);
        a0.x += x0.x; a0.y += x0.y; a0.z += x0.z; a0.w += x0.w;
        a1.x += x1.x; a1.y += x1.y; a1.z += x1.z; a1.w += x1.w;
    }
    float inv = 1.0f / (float)max(e - s, 1);
    a0.x *= inv; a0.y *= inv; a0.z *= inv; a0.w *= inv;
    a1.x *= inv; a1.y *= inv; a1.z *= inv; a1.w *= inv;
    float4* o = (float4*)(g_mean + (size_t)gw * DIM);
    o[lane] = a0;
    o[lane + 32] = a1;
}

// ---------------- fp32 -> bf16 hi/lo converters (row-major) ----------------
__device__ __forceinline__ void split8(const float* xs, uint32_t* hu, uint32_t* lu) {
    #pragma unroll
    for (int i = 0; i < 4; i++) {
        __nv_bfloat16 h0 = __float2bfloat16(xs[2 * i]);
        __nv_bfloat16 h1 = __float2bfloat16(xs[2 * i + 1]);
        __nv_bfloat16 l0 = __float2bfloat16(xs[2 * i] - __bfloat162float(h0));
        __nv_bfloat16 l1 = __float2bfloat16(xs[2 * i + 1] - __bfloat162float(h1));
        hu[i] = (uint32_t)__bfloat16_as_ushort(h0) | ((uint32_t)__bfloat16_as_ushort(h1) << 16);
        lu[i] = (uint32_t)__bfloat16_as_ushort(l0) | ((uint32_t)__bfloat16_as_ushort(l1) << 16);
    }
}

__global__ void k_convert(const float* __restrict__ src, __nv_bfloat16* __restrict__ hi,
                          __nv_bfloat16* __restrict__ lo, int n_rows) {
    int t = blockIdx.x * blockDim.x + threadIdx.x;
    if (t >= n_rows * 32) return;
    int row = t >> 5, seg = t & 31;
    const float4* p = (const float4*)(src + (size_t)row * DIM + seg * 8);
    float4 v0 = p[0], v1 = p[1];
    float xs[8] = {v0.x, v0.y, v0.z, v0.w, v1.x, v1.y, v1.z, v1.w};
    uint32_t hu[4], lu[4];
    split8(xs, hu, lu);
    size_t off = (size_t)row * DIM + seg * 8;
    *(uint4*)(hi + off) = make_uint4(hu[0], hu[1], hu[2], hu[3]);
    *(uint4*)(lo + off) = make_uint4(lu[0], lu[1], lu[2], lu[3]);
}

// W [256, N] fp32 row-major -> hi at [0, 256*N), lo at [256*N, 2*256*N)
__global__ void k_wconvert(const float* __restrict__ W, __nv_bfloat16* __restrict__ dst, int N) {
    int t = blockIdx.x * blockDim.x + threadIdx.x;
    int nseg = N >> 3;
    if (t >= 256 * nseg) return;
    int k = t / nseg, seg = t % nseg;
    const float4* p = (const float4*)(W + (size_t)k * N + seg * 8);
    float4 v0 = p[0], v1 = p[1];
    float xs[8] = {v0.x, v0.y, v0.z, v0.w, v1.x, v1.y, v1.z, v1.w};
    uint32_t hu[4], lu[4];
    split8(xs, hu, lu);
    size_t off = (size_t)k * N + seg * 8;
    *(uint4*)(dst + off) = make_uint4(hu[0], hu[1], hu[2], hu[3]);
    *(uint4*)(dst + (size_t)256 * N + off) = make_uint4(lu[0], lu[1], lu[2], lu[3]);
}

// ---------------- mma.sync bf16 GEMM ----------------
// out[M,N] = sum over 6 passes (mean/self x hi-hi, lo-hi, hi-lo), each K=256, + bias (+relu)
#define ASTRIDE_B 80      // bytes per A smem row (32 bf16 + pad 8)
#define BSTRIDE_B 272     // bytes per B smem row (128 bf16 + pad 8)
#define ABYTES (128 * ASTRIDE_B)   // 10240
#define BBYTES (32 * BSTRIDE_B)    // 8704
#define BUFBYTES (ABYTES + BBYTES) // 18944

__global__ void __launch_bounds__(256) k_gemm_mma(
    const __nv_bfloat16* __restrict__ Amh, const __nv_bfloat16* __restrict__ Aml,
    const __nv_bfloat16* __restrict__ Ash, const __nv_bfloat16* __restrict__ Asl,
    const __nv_bfloat16* __restrict__ Wn, const __nv_bfloat16* __restrict__ Ws,
    const float* __restrict__ bias, float* __restrict__ out,
    int M, int N, int relu)
{
    __shared__ __align__(16) char smem[2 * BUFBYTES];
    int tid = threadIdx.x, lane = tid & 31, wid = tid >> 5;
    int warp_m = wid >> 2, warp_n = wid & 3;
    int blkN = blockIdx.x, blkM = blockIdx.y;

    size_t wlo = (size_t)256 * N;
    const __nv_bfloat16* Ap[6] = {Amh, Aml, Amh, Ash, Asl, Ash};
    const __nv_bfloat16* Bp[6] = {Wn, Wn, Wn + wlo, Ws, Ws, Ws + wlo};

    // load assignments (2 x 16B for A, 2 x 16B for B per thread per tile)
    int rowA = tid >> 2, segA = tid & 3;
    int rowB = tid >> 4, segB = tid & 15;
    size_t gA0 = ((size_t)(blkM * 128 + rowA)) * DIM + segA * 8;
    size_t gA1 = gA0 + (size_t)64 * DIM;
    size_t gB0 = (size_t)rowB * N + blkN * 128 + segB * 8;
    size_t gB1 = gB0 + (size_t)16 * N;
    uint32_t sb = smem_u32(smem);
    uint32_t sA0 = (uint32_t)(rowA * ASTRIDE_B + segA * 16);
    uint32_t sA1 = sA0 + 64 * ASTRIDE_B;
    uint32_t sB0 = (uint32_t)(ABYTES + rowB * BSTRIDE_B + segB * 16);
    uint32_t sB1 = sB0 + 16 * BSTRIDE_B;

    float acc[4][4][4];
    #pragma unroll
    for (int m = 0; m < 4; m++)
        #pragma unroll
        for (int n = 0; n < 4; n++)
            #pragma unroll
            for (int k = 0; k < 4; k++) acc[m][n][k] = 0.f;

    // ldmatrix lane bases
    uint32_t aBase = (uint32_t)((warp_m * 64 + (lane & 15)) * ASTRIDE_B + (lane >> 4) * 16);
    uint32_t bBase = (uint32_t)(ABYTES + (lane & 15) * BSTRIDE_B + (lane >> 4) * 16 + warp_n * 64);

    #define ISSUE(it) do {                                              \
        int _p = (it) >> 3, _kk = (it) & 7;                             \
        uint32_t _d = sb + ((it) & 1) * BUFBYTES;                       \
        const __nv_bfloat16* _Ag = Ap[_p] + _kk * 32;                   \
        const __nv_bfloat16* _Bg = Bp[_p] + (size_t)_kk * 32 * N;       \
        cp16(_d + sA0, _Ag + gA0);                                      \
        cp16(_d + sA1, _Ag + gA1);                                      \
        cp16(_d + sB0, _Bg + gB0);                                      \
        cp16(_d + sB1, _Bg + gB1);                                      \
        asm volatile("cp.async.commit_group;" ::: "memory");            \
    } while (0)

    ISSUE(0);
    for (int it = 0; it < 48; ++it) {
        asm volatile("cp.async.wait_group 0;" ::: "memory");
        __syncthreads();
        if (it + 1 < 48) ISSUE(it + 1);
        uint32_t base = sb + (it & 1) * BUFBYTES;
        #pragma unroll
        for (int ks = 0; ks < 2; ks++) {
            uint32_t a[4][4], b[2][4];
            #pragma unroll
            for (int m = 0; m < 4; m++)
                ldmatrix_x4(a[m], base + aBase + m * 16 * ASTRIDE_B + ks * 32);
            #pragma unroll
            for (int n2 = 0; n2 < 2; n2++)
                ldmatrix_x4_t(b[n2], base + bBase + n2 * 32 + ks * 16 * BSTRIDE_B);
            #pragma unroll
            for (int m = 0; m < 4; m++) {
                #pragma unroll
                for (int n2 = 0; n2 < 2; n2++) {
                    mma_bf16(acc[m][2 * n2 + 0], a[m], b[n2][0], b[n2][1]);
                    mma_bf16(acc[m][2 * n2 + 1], a[m], b[n2][2], b[n2][3]);
                }
            }
        }
        __syncthreads();
    }

    // epilogue: bias + optional relu, fp32 stores
    #pragma unroll
    for (int m = 0; m < 4; m++) {
        int row0 = blkM * 128 + warp_m * 64 + m * 16 + (lane >> 2);
        int row1 = row0 + 8;
        #pragma unroll
        for (int n = 0; n < 4; n++) {
            int col = blkN * 128 + warp_n * 32 + n * 8 + (lane & 3) * 2;
            float bv0 = bias[col], bv1 = bias[col + 1];
            float v0 = acc[m][n][0] + bv0, v1 = acc[m][n][1] + bv1;
            float v2 = acc[m][n][2] + bv0, v3 = acc[m][n][3] + bv1;
            if (relu) {
                v0 = fmaxf(v0, 0.f); v1 = fmaxf(v1, 0.f);
                v2 = fmaxf(v2, 0.f); v3 = fmaxf(v3, 0.f);
            }
            if (row0 < M) *(float2*)(out + (size_t)row0 * N + col) = make_float2(v0, v1);
            if (row1 < M) *(float2*)(out + (size_t)row1 * N + col) = make_float2(v2, v3);
        }
    }
}

// ---------------- host orchestration ----------------
extern "C" void kernel_launch(void* const* d_in, const int* in_sizes, int n_in,
                              void* d_out, int out_size)
{
    const float* x   = (const float*)d_in[0];
    const float* Wn0 = (const float*)d_in[1];
    const float* Ws0 = (const float*)d_in[2];
    const float* b0  = (const float*)d_in[3];
    const float* Wn1 = (const float*)d_in[4];
    const float* Ws1 = (const float*)d_in[5];
    const float* b1  = (const float*)d_in[6];
    const float* Wn2 = (const float*)d_in[7];
    const float* Ws2 = (const float*)d_in[8];
    const float* b2  = (const float*)d_in[9];
    const int* src0 = (const int*)d_in[10];
    const int* dst0 = (const int*)d_in[11];
    const int* src1 = (const int*)d_in[12];
    const int* dst1 = (const int*)d_in[13];
    const int* src2 = (const int*)d_in[14];
    const int* dst2 = (const int*)d_in[15];
    (void)in_sizes; (void)n_in; (void)out_size;

    float *p_mean, *p_h0, *p_h1;
    __nv_bfloat16 *p_Amh, *p_Aml, *p_Ash, *p_Asl, *p_W;
    cudaGetSymbolAddress((void**)&p_mean, g_mean);
    cudaGetSymbolAddress((void**)&p_h0, g_h0);
    cudaGetSymbolAddress((void**)&p_h1, g_h1);
    cudaGetSymbolAddress((void**)&p_Amh, g_Amh);
    cudaGetSymbolAddress((void**)&p_Aml, g_Aml);
    cudaGetSymbolAddress((void**)&p_Ash, g_Ash);
    cudaGetSymbolAddress((void**)&p_Asl, g_Asl);
    cudaGetSymbolAddress((void**)&p_W, g_W);
    __nv_bfloat16* Wimg[6];
    for (int i = 0; i < 6; i++) Wimg[i] = p_W + (size_t)i * (2 * 256 * 256);

    const int E1 = 250000, E2 = 125000;

    // weight conversions (independent of graph work)
    k_wconvert<<<(256 * 32 + 255) / 256, 256>>>(Wn0, Wimg[0], 256);
    k_wconvert<<<(256 * 32 + 255) / 256, 256>>>(Ws0, Wimg[1], 256);
    k_wconvert<<<(256 * 32 + 255) / 256, 256>>>(Wn1, Wimg[2], 256);
    k_wconvert<<<(256 * 32 + 255) / 256, 256>>>(Ws1, Wimg[3], 256);
    k_wconvert<<<(256 * 16 + 255) / 256, 256>>>(Wn2, Wimg[4], 128);
    k_wconvert<<<(256 * 16 + 255) / 256, 256>>>(Ws2, Wimg[5], 128);

    // ---- layer 0 ----
    k_zero_deg<<<(ND0 + 255) / 256, 256>>>(ND0);
    k_hist<<<(E0 + 255) / 256, 256>>>(dst0, E0);
    k_scan<<<1, 1024>>>(ND0);
    k_fill<<<(E0 + 255) / 256, 256>>>(src0, dst0, E0);
    k_convert<<<(ND0 * 32 + 255) / 256, 256>>>(x, p_Ash, p_Asl, ND0);   // self = x[:ND0]
    k_aggregate<<<(ND0 + 7) / 8, 256>>>(x, ND0);
    k_convert<<<(ND0 * 32 + 255) / 256, 256>>>(p_mean, p_Amh, p_Aml, ND0);
    {
        dim3 grid(2, (ND0 + 127) / 128);
        k_gemm_mma<<<grid, 256>>>(p_Amh, p_Aml, p_Ash, p_Asl, Wimg[0], Wimg[1], b0, p_h0, ND0, 256, 1);
    }

    // ---- layer 1 ----
    k_zero_deg<<<(ND1 + 255) / 256, 256>>>(ND1);
    k_hist<<<(E1 + 255) / 256, 256>>>(dst1, E1);
    k_scan<<<1, 1024>>>(ND1);
    k_fill<<<(E1 + 255) / 256, 256>>>(src1, dst1, E1);
    k_convert<<<(ND1 * 32 + 255) / 256, 256>>>(p_h0, p_Ash, p_Asl, ND1);
    k_aggregate<<<(ND1 + 7) / 8, 256>>>(p_h0, ND1);
    k_convert<<<(ND1 * 32 + 255) / 256, 256>>>(p_mean, p_Amh, p_Aml, ND1);
    {
        dim3 grid(2, (ND1 + 127) / 128);
        k_gemm_mma<<<grid, 256>>>(p_Amh, p_Aml, p_Ash, p_Asl, Wimg[2], Wimg[3], b1, p_h1, ND1, 256, 1);
    }

    // ---- layer 2 ----
    k_zero_deg<<<(ND2 + 255) / 256, 256>>>(ND2);
    k_hist<<<(E2 + 255) / 256, 256>>>(dst2, E2);
    k_scan<<<1, 1024>>>(ND2);
    k_fill<<<(E2 + 255) / 256, 256>>>(src2, dst2, E2);
    k_convert<<<(ND2 * 32 + 255) / 256, 256>>>(p_h1, p_Ash, p_Asl, ND2);
    k_aggregate<<<(ND2 + 7) / 8, 256>>>(p_h1, ND2);
    k_convert<<<(ND2 * 32 + 255) / 256, 256>>>(p_mean, p_Amh, p_Aml, ND2);
    {
        dim3 grid(1, (ND2 + 127) / 128);
        k_gemm_mma<<<grid, 256>>>(p_Amh, p_Aml, p_Ash, p_Asl, Wimg[4], Wimg[5], b2, (float*)d_out, ND2, 128, 0);
    }
}

// round 7
// speedup vs baseline: 2.2435x; 1.3782x over previous
#include <cuda_runtime.h>
#include <cuda_bf16.h>
#include <cstdint>

// ---------------- problem constants ----------------
#define ND0 50000
#define ND1 25000
#define ND2 12500
#define NDT (ND0 + ND1 + ND2)          // 87500
#define E0  500000
#define E1  250000
#define E2  125000
#define ET  (E0 + E1 + E2)             // 875000
#define DIM 256
#define NB0 391
#define MAXROWS (NB0 * 128)            // 50048

// scan block layout
#define NBL0 49                        // ceil(ND0/1024)
#define NBL1 25
#define NBL2 13
#define TOTB (NBL0 + NBL1 + NBL2)      // 87
#define RP0 0
#define RP1 (ND0 + 1)
#define RP2 (ND0 + ND1 + 2)

// ---------------- device scratch (static, no allocs) ----------------
__device__ float g_h0[(size_t)ND0 * DIM];
__device__ float g_h1[(size_t)ND1 * DIM];
__device__ int g_deg[NDT];
__device__ int g_rowptr[NDT + 3];
__device__ int g_cursor[NDT];
__device__ int g_srcidx[ET];
__device__ int g_bsum[TOTB];
__device__ int g_bscan[TOTB];
// operand images, row-major [MAXROWS, 256] bf16
__device__ __align__(16) __nv_bfloat16 g_Amh[(size_t)MAXROWS * DIM];   // mean hi
__device__ __align__(16) __nv_bfloat16 g_Aml[(size_t)MAXROWS * DIM];   // mean lo
__device__ __align__(16) __nv_bfloat16 g_iAh[(size_t)MAXROWS * DIM];   // self img A hi
__device__ __align__(16) __nv_bfloat16 g_iAl[(size_t)MAXROWS * DIM];
__device__ __align__(16) __nv_bfloat16 g_iBh[(size_t)MAXROWS * DIM];   // self img B hi
__device__ __align__(16) __nv_bfloat16 g_iBl[(size_t)MAXROWS * DIM];
// weight images: 6 matrices, each hi[256*N] then lo[256*N]
__device__ __align__(16) __nv_bfloat16 g_W[6][2 * 256 * 256];

// ---------------- helpers ----------------
__device__ __forceinline__ uint32_t smem_u32(const void* p) {
    uint32_t a;
    asm("{ .reg .u64 t; cvta.to.shared.u64 t, %1; cvt.u32.u64 %0, t; }" : "=r"(a) : "l"(p));
    return a;
}
__device__ __forceinline__ void cp16(uint32_t dst, const void* src) {
    asm volatile("cp.async.cg.shared.global [%0], [%1], 16;" :: "r"(dst), "l"(src) : "memory");
}
__device__ __forceinline__ void ldmatrix_x4(uint32_t* r, uint32_t addr) {
    asm volatile("ldmatrix.sync.aligned.m8n8.x4.shared.b16 {%0,%1,%2,%3}, [%4];"
                 : "=r"(r[0]), "=r"(r[1]), "=r"(r[2]), "=r"(r[3]) : "r"(addr));
}
__device__ __forceinline__ void ldmatrix_x4_t(uint32_t* r, uint32_t addr) {
    asm volatile("ldmatrix.sync.aligned.m8n8.x4.trans.shared.b16 {%0,%1,%2,%3}, [%4];"
                 : "=r"(r[0]), "=r"(r[1]), "=r"(r[2]), "=r"(r[3]) : "r"(addr));
}
__device__ __forceinline__ void mma_bf16(float* c, const uint32_t* a, uint32_t b0, uint32_t b1) {
    asm volatile(
        "mma.sync.aligned.m16n8k16.row.col.f32.bf16.bf16.f32 "
        "{%0,%1,%2,%3}, {%4,%5,%6,%7}, {%8,%9}, {%0,%1,%2,%3};"
        : "+f"(c[0]), "+f"(c[1]), "+f"(c[2]), "+f"(c[3])
        : "r"(a[0]), "r"(a[1]), "r"(a[2]), "r"(a[3]), "r"(b0), "r"(b1));
}
__device__ __forceinline__ uint32_t pack_hi(float a, float b) {
    return (uint32_t)__bfloat16_as_ushort(__float2bfloat16(a)) |
           ((uint32_t)__bfloat16_as_ushort(__float2bfloat16(b)) << 16);
}
__device__ __forceinline__ uint32_t pack_lo(float a, float b) {
    float ra = a - __bfloat162float(__float2bfloat16(a));
    float rb = b - __bfloat162float(__float2bfloat16(b));
    return (uint32_t)__bfloat16_as_ushort(__float2bfloat16(ra)) |
           ((uint32_t)__bfloat16_as_ushort(__float2bfloat16(rb)) << 16);
}
__device__ __forceinline__ void blkmap(int b, int& layer, int& chunk, int& degoff, int& nd, int& rpoff) {
    if (b < NBL0)             { layer = 0; chunk = b;            degoff = 0;         nd = ND0; rpoff = RP0; }
    else if (b < NBL0 + NBL1) { layer = 1; chunk = b - NBL0;     degoff = ND0;       nd = ND1; rpoff = RP1; }
    else                      { layer = 2; chunk = b - NBL0 - NBL1; degoff = ND0 + ND1; nd = ND2; rpoff = RP2; }
}

// ---------------- CSR build (all 3 layers) ----------------
__global__ void k_zero_all() {
    int i = blockIdx.x * blockDim.x + threadIdx.x;
    if (i < NDT) g_deg[i] = 0;
}
__global__ void k_hist_all(const int* __restrict__ d0, const int* __restrict__ d1,
                           const int* __restrict__ d2) {
    int i = blockIdx.x * blockDim.x + threadIdx.x;
    if (i < E0) atomicAdd(&g_deg[d0[i]], 1);
    else if (i < E0 + E1) atomicAdd(&g_deg[ND0 + d1[i - E0]], 1);
    else if (i < ET) atomicAdd(&g_deg[ND0 + ND1 + d2[i - E0 - E1]], 1);
}
__global__ void k_bsum() {
    __shared__ int s[1024];
    int layer, chunk, degoff, nd, rpoff;
    blkmap(blockIdx.x, layer, chunk, degoff, nd, rpoff);
    int idx = chunk * 1024 + threadIdx.x;
    int v = (idx < nd) ? g_deg[degoff + idx] : 0;
    s[threadIdx.x] = v;
    __syncthreads();
    for (int off = 512; off > 0; off >>= 1) {
        if (threadIdx.x < off) s[threadIdx.x] += s[threadIdx.x + off];
        __syncthreads();
    }
    if (threadIdx.x == 0) g_bsum[blockIdx.x] = s[0];
}
__global__ void k_scanb() {
    int t = threadIdx.x;
    if (t == 0) {
        int c = 0;
        for (int b = 0; b < NBL0; b++) { g_bscan[b] = c; c += g_bsum[b]; }
        g_rowptr[RP0 + ND0] = c;
    } else if (t == 1) {
        int c = 0;
        for (int b = NBL0; b < NBL0 + NBL1; b++) { g_bscan[b] = c; c += g_bsum[b]; }
        g_rowptr[RP1 + ND1] = c;
    } else if (t == 2) {
        int c = 0;
        for (int b = NBL0 + NBL1; b < TOTB; b++) { g_bscan[b] = c; c += g_bsum[b]; }
        g_rowptr[RP2 + ND2] = c;
    }
}
__global__ void k_scanfinal() {
    __shared__ int s[1024];
    int layer, chunk, degoff, nd, rpoff;
    blkmap(blockIdx.x, layer, chunk, degoff, nd, rpoff);
    int idx = chunk * 1024 + threadIdx.x;
    int v = (idx < nd) ? g_deg[degoff + idx] : 0;
    s[threadIdx.x] = v;
    __syncthreads();
    #pragma unroll
    for (int off = 1; off < 1024; off <<= 1) {
        int t = (threadIdx.x >= off) ? s[threadIdx.x - off] : 0;
        __syncthreads();
        s[threadIdx.x] += t;
        __syncthreads();
    }
    if (idx < nd) {
        int val = g_bscan[blockIdx.x] + s[threadIdx.x] - v;
        g_rowptr[rpoff + idx] = val;
        g_cursor[degoff + idx] = val;
    }
}
__global__ void k_fill_all(const int* __restrict__ s0, const int* __restrict__ d0,
                           const int* __restrict__ s1, const int* __restrict__ d1,
                           const int* __restrict__ s2, const int* __restrict__ d2) {
    int i = blockIdx.x * blockDim.x + threadIdx.x;
    if (i < E0) {
        int pos = atomicAdd(&g_cursor[d0[i]], 1);
        g_srcidx[pos] = s0[i];
    } else if (i < E0 + E1) {
        int j = i - E0;
        int pos = atomicAdd(&g_cursor[ND0 + d1[j]], 1);
        g_srcidx[E0 + pos] = s1[j];
    } else if (i < ET) {
        int j = i - E0 - E1;
        int pos = atomicAdd(&g_cursor[ND0 + ND1 + d2[j]], 1);
        g_srcidx[E0 + E1 + pos] = s2[j];
    }
}

// ---------------- aggregation: warp per row, fused bf16 hi/lo split ----------------
__global__ void k_aggregate(const float* __restrict__ h,
                            __nv_bfloat16* __restrict__ mh, __nv_bfloat16* __restrict__ ml,
                            const int* __restrict__ rowptr, const int* __restrict__ srcidx,
                            int n_dst) {
    int gw = (blockIdx.x * blockDim.x + threadIdx.x) >> 5;
    int lane = threadIdx.x & 31;
    if (gw >= n_dst) return;
    int s = rowptr[gw], e = rowptr[gw + 1];
    float4 a0 = make_float4(0.f, 0.f, 0.f, 0.f);
    float4 a1 = make_float4(0.f, 0.f, 0.f, 0.f);
    for (int i = s; i < e; i++) {
        const float4* row = (const float4*)(h + (size_t)srcidx[i] * DIM);
        float4 x0 = __ldg(&row[lane]);
        float4 x1 = __ldg(&row[lane + 32]);
        a0.x += x0.x; a0.y += x0.y; a0.z += x0.z; a0.w += x0.w;
        a1.x += x1.x; a1.y += x1.y; a1.z += x1.z; a1.w += x1.w;
    }
    float inv = 1.0f / (float)max(e - s, 1);
    a0.x *= inv; a0.y *= inv; a0.z *= inv; a0.w *= inv;
    a1.x *= inv; a1.y *= inv; a1.z *= inv; a1.w *= inv;
    size_t off0 = (size_t)gw * DIM + lane * 4;
    size_t off1 = off0 + 128;
    *(uint2*)(mh + off0) = make_uint2(pack_hi(a0.x, a0.y), pack_hi(a0.z, a0.w));
    *(uint2*)(ml + off0) = make_uint2(pack_lo(a0.x, a0.y), pack_lo(a0.z, a0.w));
    *(uint2*)(mh + off1) = make_uint2(pack_hi(a1.x, a1.y), pack_hi(a1.z, a1.w));
    *(uint2*)(ml + off1) = make_uint2(pack_lo(a1.x, a1.y), pack_lo(a1.z, a1.w));
}

// ---------------- x -> self hi/lo images ----------------
__global__ void k_convert(const float* __restrict__ src, __nv_bfloat16* __restrict__ hi,
                          __nv_bfloat16* __restrict__ lo, int n_rows) {
    int t = blockIdx.x * blockDim.x + threadIdx.x;
    if (t >= n_rows * 32) return;
    int row = t >> 5, seg = t & 31;
    const float4* p = (const float4*)(src + (size_t)row * DIM + seg * 8);
    float4 v0 = p[0], v1 = p[1];
    size_t off = (size_t)row * DIM + seg * 8;
    *(uint4*)(hi + off) = make_uint4(pack_hi(v0.x, v0.y), pack_hi(v0.z, v0.w),
                                     pack_hi(v1.x, v1.y), pack_hi(v1.z, v1.w));
    *(uint4*)(lo + off) = make_uint4(pack_lo(v0.x, v0.y), pack_lo(v0.z, v0.w),
                                     pack_lo(v1.x, v1.y), pack_lo(v1.z, v1.w));
}

// ---------------- all 6 weights -> hi/lo images in one kernel ----------------
__global__ void k_wconvert_all(const float* __restrict__ w0, const float* __restrict__ w1,
                               const float* __restrict__ w2, const float* __restrict__ w3,
                               const float* __restrict__ w4, const float* __restrict__ w5) {
    int t = blockIdx.x * blockDim.x + threadIdx.x;
    int wi, rem, N;
    if (t < 4 * 8192) { wi = t >> 13; rem = t & 8191; N = 256; }
    else if (t < 4 * 8192 + 2 * 4096) { int u = t - 4 * 8192; wi = 4 + (u >> 12); rem = u & 4095; N = 128; }
    else return;
    const float* W = (wi == 0) ? w0 : (wi == 1) ? w1 : (wi == 2) ? w2 : (wi == 3) ? w3 : (wi == 4) ? w4 : w5;
    int nseg = N >> 3;
    int k = rem / nseg, seg = rem % nseg;
    const float4* p = (const float4*)(W + (size_t)k * N + seg * 8);
    float4 v0 = p[0], v1 = p[1];
    __nv_bfloat16* dst = &g_W[wi][0];
    size_t off = (size_t)k * N + seg * 8;
    *(uint4*)(dst + off) = make_uint4(pack_hi(v0.x, v0.y), pack_hi(v0.z, v0.w),
                                      pack_hi(v1.x, v1.y), pack_hi(v1.z, v1.w));
    *(uint4*)(dst + (size_t)256 * N + off) = make_uint4(pack_lo(v0.x, v0.y), pack_lo(v0.z, v0.w),
                                                        pack_lo(v1.x, v1.y), pack_lo(v1.z, v1.w));
}

// ---------------- mma.sync bf16 GEMM, 3-stage cp.async pipeline ----------------
#define ASTRIDE_B 80
#define BSTRIDE_B 272
#define ABYTES (128 * ASTRIDE_B)        // 10240
#define BBYTES (32 * BSTRIDE_B)         // 8704
#define BUFBYTES (ABYTES + BBYTES)      // 18944
#define STAGES 3
#define SMEM_TOT (STAGES * BUFBYTES)    // 56832

__global__ void __launch_bounds__(256) k_gemm_mma(
    const __nv_bfloat16* __restrict__ Amh, const __nv_bfloat16* __restrict__ Aml,
    const __nv_bfloat16* __restrict__ Ash, const __nv_bfloat16* __restrict__ Asl,
    const __nv_bfloat16* __restrict__ Wn, const __nv_bfloat16* __restrict__ Ws,
    const float* __restrict__ bias, float* __restrict__ out,
    __nv_bfloat16* __restrict__ selfH, __nv_bfloat16* __restrict__ selfL,
    int M, int N, int relu)
{
    extern __shared__ __align__(16) char smem[];
    int tid = threadIdx.x, lane = tid & 31, wid = tid >> 5;
    int warp_m = wid >> 2, warp_n = wid & 3;
    int blkN = blockIdx.x, blkM = blockIdx.y;

    size_t wlo = (size_t)256 * N;
    const __nv_bfloat16* Ap[6] = {Amh, Aml, Amh, Ash, Asl, Ash};
    const __nv_bfloat16* Bp[6] = {Wn, Wn, Wn + wlo, Ws, Ws, Ws + wlo};

    int rowA = tid >> 2, segA = tid & 3;
    int rowB = tid >> 4, segB = tid & 15;
    size_t gA0 = ((size_t)(blkM * 128 + rowA)) * DIM + segA * 8;
    size_t gA1 = gA0 + (size_t)64 * DIM;
    size_t gB0 = (size_t)rowB * N + blkN * 128 + segB * 8;
    size_t gB1 = gB0 + (size_t)16 * N;
    uint32_t sb = smem_u32(smem);
    uint32_t sA0 = (uint32_t)(rowA * ASTRIDE_B + segA * 16);
    uint32_t sA1 = sA0 + 64 * ASTRIDE_B;
    uint32_t sB0 = (uint32_t)(ABYTES + rowB * BSTRIDE_B + segB * 16);
    uint32_t sB1 = sB0 + 16 * BSTRIDE_B;

    float acc[4][4][4];
    #pragma unroll
    for (int m = 0; m < 4; m++)
        #pragma unroll
        for (int n = 0; n < 4; n++)
            #pragma unroll
            for (int k = 0; k < 4; k++) acc[m][n][k] = 0.f;

    uint32_t aBase = (uint32_t)((warp_m * 64 + (lane & 15)) * ASTRIDE_B + (lane >> 4) * 16);
    uint32_t bBase = (uint32_t)(ABYTES + (lane & 15) * BSTRIDE_B + (lane >> 4) * 16 + warp_n * 64);

    #define ISSUE(it) do {                                              \
        int _p = (it) >> 3, _kk = (it) & 7;                             \
        uint32_t _d = sb + ((it) % STAGES) * BUFBYTES;                  \
        const __nv_bfloat16* _Ag = Ap[_p] + _kk * 32;                   \
        const __nv_bfloat16* _Bg = Bp[_p] + (size_t)_kk * 32 * N;       \
        cp16(_d + sA0, _Ag + gA0);                                      \
        cp16(_d + sA1, _Ag + gA1);                                      \
        cp16(_d + sB0, _Bg + gB0);                                      \
        cp16(_d + sB1, _Bg + gB1);                                      \
        asm volatile("cp.async.commit_group;" ::: "memory");            \
    } while (0)

    ISSUE(0);
    ISSUE(1);
    for (int it = 0; it < 48; ++it) {
        asm volatile("cp.async.wait_group 1;" ::: "memory");
        __syncthreads();
        if (it + 2 < 48) ISSUE(it + 2);
        uint32_t base = sb + (it % STAGES) * BUFBYTES;
        #pragma unroll
        for (int ks = 0; ks < 2; ks++) {
            uint32_t a[4][4], b[2][4];
            #pragma unroll
            for (int m = 0; m < 4; m++)
                ldmatrix_x4(a[m], base + aBase + m * 16 * ASTRIDE_B + ks * 32);
            #pragma unroll
            for (int n2 = 0; n2 < 2; n2++)
                ldmatrix_x4_t(b[n2], base + bBase + n2 * 32 + ks * 16 * BSTRIDE_B);
            #pragma unroll
            for (int m = 0; m < 4; m++) {
                #pragma unroll
                for (int n2 = 0; n2 < 2; n2++) {
                    mma_bf16(acc[m][2 * n2 + 0], a[m], b[n2][0], b[n2][1]);
                    mma_bf16(acc[m][2 * n2 + 1], a[m], b[n2][2], b[n2][3]);
                }
            }
        }
    }

    // epilogue: bias (+relu), fp32 h store, optional next-layer self hi/lo store
    #pragma unroll
    for (int m = 0; m < 4; m++) {
        int row0 = blkM * 128 + warp_m * 64 + m * 16 + (lane >> 2);
        int row1 = row0 + 8;
        #pragma unroll
        for (int n = 0; n < 4; n++) {
            int col = blkN * 128 + warp_n * 32 + n * 8 + (lane & 3) * 2;
            float bv0 = bias[col], bv1 = bias[col + 1];
            float v0 = acc[m][n][0] + bv0, v1 = acc[m][n][1] + bv1;
            float v2 = acc[m][n][2] + bv0, v3 = acc[m][n][3] + bv1;
            if (relu) {
                v0 = fmaxf(v0, 0.f); v1 = fmaxf(v1, 0.f);
                v2 = fmaxf(v2, 0.f); v3 = fmaxf(v3, 0.f);
            }
            if (row0 < M) {
                *(float2*)(out + (size_t)row0 * N + col) = make_float2(v0, v1);
                if (selfH) {
                    *(uint32_t*)(selfH + (size_t)row0 * N + col) = pack_hi(v0, v1);
                    *(uint32_t*)(selfL + (size_t)row0 * N + col) = pack_lo(v0, v1);
                }
            }
            if (row1 < M) {
                *(float2*)(out + (size_t)row1 * N + col) = make_float2(v2, v3);
                if (selfH) {
                    *(uint32_t*)(selfH + (size_t)row1 * N + col) = pack_hi(v2, v3);
                    *(uint32_t*)(selfL + (size_t)row1 * N + col) = pack_lo(v2, v3);
                }
            }
        }
    }
}

// ---------------- host orchestration ----------------
extern "C" void kernel_launch(void* const* d_in, const int* in_sizes, int n_in,
                              void* d_out, int out_size)
{
    const float* x   = (const float*)d_in[0];
    const float* Wn0 = (const float*)d_in[1];
    const float* Ws0 = (const float*)d_in[2];
    const float* b0  = (const float*)d_in[3];
    const float* Wn1 = (const float*)d_in[4];
    const float* Ws1 = (const float*)d_in[5];
    const float* b1  = (const float*)d_in[6];
    const float* Wn2 = (const float*)d_in[7];
    const float* Ws2 = (const float*)d_in[8];
    const float* b2  = (const float*)d_in[9];
    const int* src0 = (const int*)d_in[10];
    const int* dst0 = (const int*)d_in[11];
    const int* src1 = (const int*)d_in[12];
    const int* dst1 = (const int*)d_in[13];
    const int* src2 = (const int*)d_in[14];
    const int* dst2 = (const int*)d_in[15];
    (void)in_sizes; (void)n_in; (void)out_size;

    cudaFuncSetAttribute(k_gemm_mma, cudaFuncAttributeMaxDynamicSharedMemorySize, SMEM_TOT);

    float *p_h0, *p_h1;
    __nv_bfloat16 *p_Amh, *p_Aml, *p_iAh, *p_iAl, *p_iBh, *p_iBl, *p_W;
    int *p_rp, *p_si;
    cudaGetSymbolAddress((void**)&p_h0, g_h0);
    cudaGetSymbolAddress((void**)&p_h1, g_h1);
    cudaGetSymbolAddress((void**)&p_Amh, g_Amh);
    cudaGetSymbolAddress((void**)&p_Aml, g_Aml);
    cudaGetSymbolAddress((void**)&p_iAh, g_iAh);
    cudaGetSymbolAddress((void**)&p_iAl, g_iAl);
    cudaGetSymbolAddress((void**)&p_iBh, g_iBh);
    cudaGetSymbolAddress((void**)&p_iBl, g_iBl);
    cudaGetSymbolAddress((void**)&p_W, g_W);
    cudaGetSymbolAddress((void**)&p_rp, g_rowptr);
    cudaGetSymbolAddress((void**)&p_si, g_srcidx);
    __nv_bfloat16* Wimg[6];
    for (int i = 0; i < 6; i++) Wimg[i] = p_W + (size_t)i * (2 * 256 * 256);

    // ---- CSR build for all 3 layers ----
    k_zero_all<<<(NDT + 255) / 256, 256>>>();
    k_hist_all<<<(ET + 255) / 256, 256>>>(dst0, dst1, dst2);
    k_bsum<<<TOTB, 1024>>>();
    k_scanb<<<1, 32>>>();
    k_scanfinal<<<TOTB, 1024>>>();
    k_fill_all<<<(ET + 255) / 256, 256>>>(src0, dst0, src1, dst1, src2, dst2);

    // ---- weight + x conversions ----
    k_wconvert_all<<<(4 * 8192 + 2 * 4096 + 255) / 256, 256>>>(Wn0, Ws0, Wn1, Ws1, Wn2, Ws2);
    k_convert<<<(ND0 * 32 + 255) / 256, 256>>>(x, p_iAh, p_iAl, ND0);

    // ---- layer 0: self=imgA(x), writes h0 + imgB ----
    k_aggregate<<<(ND0 + 7) / 8, 256>>>(x, p_Amh, p_Aml, p_rp + RP0, p_si, ND0);
    {
        dim3 grid(2, (ND0 + 127) / 128);
        k_gemm_mma<<<grid, 256, SMEM_TOT>>>(p_Amh, p_Aml, p_iAh, p_iAl, Wimg[0], Wimg[1],
                                            b0, p_h0, p_iBh, p_iBl, ND0, 256, 1);
    }
    // ---- layer 1: self=imgB(h0), writes h1 + imgA ----
    k_aggregate<<<(ND1 + 7) / 8, 256>>>(p_h0, p_Amh, p_Aml, p_rp + RP1, p_si + E0, ND1);
    {
        dim3 grid(2, (ND1 + 127) / 128);
        k_gemm_mma<<<grid, 256, SMEM_TOT>>>(p_Amh, p_Aml, p_iBh, p_iBl, Wimg[2], Wimg[3],
                                            b1, p_h1, p_iAh, p_iAl, ND1, 256, 1);
    }
    // ---- layer 2: self=imgA(h1), writes d_out ----
    k_aggregate<<<(ND2 + 7) / 8, 256>>>(p_h1, p_Amh, p_Aml, p_rp + RP2, p_si + E0 + E1, ND2);
    {
        dim3 grid(1, (ND2 + 127) / 128);
        k_gemm_mma<<<grid, 256, SMEM_TOT>>>(p_Amh, p_Aml, p_iAh, p_iAl, Wimg[4], Wimg[5],
                                            b2, (float*)d_out, nullptr, nullptr, ND2, 128, 0);
    }
}